// round 15
// baseline (speedup 1.0000x reference)
#include <cuda_runtime.h>
#include <cuda_bf16.h>
#include <cuda_fp8.h>
#include <cstdint>

// Problem shape (fixed by the dataset): M=8192 (B*T), K=4096 (C), N=16384 (O)
#define MAX_M 8192
#define MAX_K 4096
#define MAX_N 16384

// bf16 scratch holding fp8-quantized values (e4m3 -> bf16 is exact)
__device__ __align__(128) __nv_bfloat16 g_Xb[(size_t)MAX_M * MAX_K];  //  64 MB
__device__ __align__(128) __nv_bfloat16 g_Wb[(size_t)MAX_N * MAX_K];  // 128 MB

// ----------------------------- helpers -------------------------------------
__device__ __forceinline__ uint32_t smem_u32(const void* p) {
    uint32_t a;
    asm("{ .reg .u64 t; cvta.to.shared.u64 t, %1; cvt.u32.u64 %0, t; }"
        : "=r"(a) : "l"(p));
    return a;
}

#define CP_ASYNC16(saddr, gptr) \
    asm volatile("cp.async.cg.shared.global [%0], [%1], 16;" :: "r"(saddr), "l"(gptr))
#define CP_COMMIT() asm volatile("cp.async.commit_group;" ::: "memory")
#define CP_WAIT(n)  asm volatile("cp.async.wait_group %0;" :: "n"(n) : "memory")

__device__ __forceinline__ void ldsm_x4(uint32_t* r, uint32_t addr) {
    asm volatile("ldmatrix.sync.aligned.m8n8.x4.shared.b16 {%0,%1,%2,%3}, [%4];"
                 : "=r"(r[0]), "=r"(r[1]), "=r"(r[2]), "=r"(r[3]) : "r"(addr));
}

// bf16 x bf16 -> f32 MMA (sm_80+)
__device__ __forceinline__ void mma_bf16(float* c, const uint32_t* a, const uint32_t* b) {
    asm volatile(
        "mma.sync.aligned.m16n8k16.row.col.f32.bf16.bf16.f32 "
        "{%0,%1,%2,%3}, {%4,%5,%6,%7}, {%8,%9}, {%0,%1,%2,%3};"
        : "+f"(c[0]), "+f"(c[1]), "+f"(c[2]), "+f"(c[3])
        : "r"(a[0]), "r"(a[1]), "r"(a[2]), "r"(a[3]), "r"(b[0]), "r"(b[1]));
}

// streaming (evict-first) scratch store: write-once, re-read much later
__device__ __forceinline__ void stg_cs_u4(uint4* p, uint4 v) {
    asm volatile("st.global.cs.v4.b32 [%0], {%1, %2, %3, %4};"
                 :: "l"(p), "r"(v.x), "r"(v.y), "r"(v.z), "r"(v.w) : "memory");
}

// streaming (evict-first) float2 store: out is write-once, keep it out of L2
__device__ __forceinline__ void stg_cs_f2(float* p, float a, float b) {
    asm volatile("st.global.cs.v2.f32 [%0], {%1, %2};"
                 :: "l"(p), "f"(a), "f"(b) : "memory");
}

// ------------------------------ constants -----------------------------------
// CTA tile 256x128, 8 warps (4M x 2N), warp tile 64x64. Persistent CTAs.
#define BM 256
#define BN 128
#define BKB 128                                 // chunk K-bytes per row
#define STAGES 4
#define STAGE_A (BM * BKB)                      // 32768
#define STAGE_B (BN * BKB)                      // 16384
#define STAGE_BYTES (STAGE_A + STAGE_B)         // 49152
#define SMEM_TOTAL (STAGES * STAGE_BYTES)       // 196608
#define GRP 8

// ------------------------------ quantize ------------------------------------
// x -> clamp/round to e4m3 (satfinite) -> bf16 (exact). Matches reference
// fp8 quantize->dequantize semantics bit-for-bit.
__device__ __forceinline__ uint32_t q2bf(float a, float b) {
    __nv_fp8x2_storage_t p8 =
        __nv_cvt_float2_to_fp8x2(make_float2(a, b), __NV_SATFINITE, __NV_E4M3);
    __half2_raw hr = __nv_cvt_fp8x2_to_halfraw2(p8, __NV_E4M3);   // exact
    __half2 h = *reinterpret_cast<__half2*>(&hr);
    float2 f = __half22float2(h);                                  // exact
    __nv_bfloat162 bb = __float22bfloat162_rn(f);                  // exact (e4m3)
    return *reinterpret_cast<uint32_t*>(&bb);
}

// each thread: 2 adjacent float4 reads (32B) -> 1 uint4 streaming write (16B)
__global__ void quant_fused_kernel(const float* __restrict__ x,
                                   const float* __restrict__ w,
                                   uint4* __restrict__ xb,
                                   uint4* __restrict__ wb,
                                   int n8x, int n8w) {
    int i = blockIdx.x * blockDim.x + threadIdx.x;
    if (i < n8x) {
        float4 v0 = ((const float4*)x)[2 * i];
        float4 v1 = ((const float4*)x)[2 * i + 1];
        stg_cs_u4(xb + i, make_uint4(q2bf(v0.x, v0.y), q2bf(v0.z, v0.w),
                                     q2bf(v1.x, v1.y), q2bf(v1.z, v1.w)));
    } else {
        int j = i - n8x;
        if (j < n8w) {
            float4 v0 = ((const float4*)w)[2 * j];
            float4 v1 = ((const float4*)w)[2 * j + 1];
            stg_cs_u4(wb + j, make_uint4(q2bf(v0.x, v0.y), q2bf(v0.z, v0.w),
                                         q2bf(v1.x, v1.y), q2bf(v1.z, v1.w)));
        }
    }
}

// grouped rasterization: tile id -> (m0, n0)
__device__ __forceinline__ void tile_coords(int t, int tiles_m, int tiles_n,
                                            int& m0, int& n0) {
    int tpg = GRP * tiles_n;
    int g = t / tpg, r = t % tpg;
    int mf = g * GRP;
    int gs = tiles_m - mf; if (gs > GRP) gs = GRP;
    m0 = (mf + (r % gs)) * BM;
    n0 = (r / gs) * BN;
}

// ------------------------------- GEMM ----------------------------------------
__global__ void __launch_bounds__(256, 1)
fp8_gemm_kernel(const float* __restrict__ bias, float* __restrict__ out,
                int M, int N, int K) {
    extern __shared__ char smem[];
    const uint32_t sbase = smem_u32(smem);
    const int tid  = threadIdx.x;
    const int wid  = tid >> 5;
    const int lane = tid & 31;
    const int wm = wid & 3;    // 4 M-warps x 64 rows
    const int wn = wid >> 2;   // 2 N-warps x 64 cols

    const int tiles_m = M / BM;   // 32
    const int tiles_n = N / BN;   // 128
    const int ntiles  = tiles_m * tiles_n;
    const int G = gridDim.x;
    const size_t rowbytes = (size_t)K * 2;
    const int NC = (K * 2) / BKB;   // 64 chunks of 64 bf16

    // ---- load-side cursor (rolls across tile boundaries) ----
    int t_load = blockIdx.x;
    int ck_load = 0;
    const uint8_t *lAg, *lBg;
    {
        int m0l, n0l; tile_coords(t_load, tiles_m, tiles_n, m0l, n0l);
        lAg = (const uint8_t*)g_Xb + (size_t)m0l * rowbytes;
        lBg = (const uint8_t*)g_Wb + (size_t)n0l * rowbytes;
    }

    // one K-chunk: 3072 x 16B units (A 2048 + B 1024); 12 per thread.
    // smem rows 128B; swizzle cu = c ^ (row & 7) -> conflict-free.
    auto issue_load = [&]() {
        if (t_load < ntiles) {
            const uint32_t st = sbase + (ck_load & 3) * STAGE_BYTES;
            const int ck = ck_load;
#pragma unroll
            for (int j = 0; j < 12; j++) {
                int u = tid + 256 * j;
                if (u < 2048) {
                    int row = u >> 3, c = u & 7;
                    CP_ASYNC16(st + row * 128 + ((c ^ (row & 7)) << 4),
                               lAg + (size_t)row * rowbytes + ck * BKB + c * 16);
                } else {
                    int v = u - 2048;
                    int row = v >> 3, c = v & 7;
                    CP_ASYNC16(st + STAGE_A + row * 128 + ((c ^ (row & 7)) << 4),
                               lBg + (size_t)row * rowbytes + ck * BKB + c * 16);
                }
            }
            if (++ck_load == NC) {
                ck_load = 0;
                t_load += G;
                if (t_load < ntiles) {
                    int m0l, n0l; tile_coords(t_load, tiles_m, tiles_n, m0l, n0l);
                    lAg = (const uint8_t*)g_Xb + (size_t)m0l * rowbytes;
                    lBg = (const uint8_t*)g_Wb + (size_t)n0l * rowbytes;
                }
            }
        }
        CP_COMMIT();
    };

    // lane-derived ldmatrix address components (mapping verified rel_err=0)
    const int lr   = lane & 7;
    const int lsel = lane >> 3;                 // 0..3
    const int a_row_off = lr + (lsel & 1) * 8;  // A: bit0 -> +8 rows
    const int a_ku      = lsel >> 1;            //    bit1 -> k-unit
    const int b_ni_off  = lsel >> 1;            // B: bit1 -> n8 within pair
    const int b_ku      = lsel & 1;             //    bit0 -> k-unit
    const uint32_t a_base = (uint32_t)(wm * 64 + a_row_off) * 128;
    const uint32_t b_base = STAGE_A + (uint32_t)(wn * 64 + b_ni_off * 8 + lr) * 128;

    float acc[4][8][4];
    uint32_t afr[2][4][4];
    uint32_t bfr[8][2];

    auto ldA = [&](int buf, int ks, int pb) {
        const uint32_t s = sbase + buf * STAGE_BYTES + a_base
                         + ((((ks << 1) | a_ku) ^ lr) << 4);
#pragma unroll
        for (int mi = 0; mi < 4; mi++)
            ldsm_x4(afr[pb][mi], s + mi * 2048);
    };
    auto ldB0 = [&](int buf, int ks) {
        const uint32_t s = sbase + buf * STAGE_BYTES + b_base
                         + ((((ks << 1) | b_ku) ^ lr) << 4);
        uint32_t t[4];
        ldsm_x4(t, s);
        bfr[0][0] = t[0]; bfr[0][1] = t[1]; bfr[1][0] = t[2]; bfr[1][1] = t[3];
        ldsm_x4(t, s + 2048);
        bfr[2][0] = t[0]; bfr[2][1] = t[1]; bfr[3][0] = t[2]; bfr[3][1] = t[3];
    };
    auto ldB1 = [&](int buf, int ks) {
        const uint32_t s = sbase + buf * STAGE_BYTES + b_base
                         + ((((ks << 1) | b_ku) ^ lr) << 4);
        uint32_t t[4];
        ldsm_x4(t, s + 4096);
        bfr[4][0] = t[0]; bfr[4][1] = t[1]; bfr[5][0] = t[2]; bfr[5][1] = t[3];
        ldsm_x4(t, s + 6144);
        bfr[6][0] = t[0]; bfr[6][1] = t[1]; bfr[7][0] = t[2]; bfr[7][1] = t[3];
    };

    // ---- prologue: 2 chunks in flight, prime first window ----
    issue_load();
    issue_load();
    CP_WAIT(0);
    __syncthreads();
    ldA(0, 0, 0); ldB0(0, 0);

    // ---- persistent tile loop ----
    for (int t = blockIdx.x; t < ntiles; t += G) {
#pragma unroll
        for (int mi = 0; mi < 4; mi++)
#pragma unroll
            for (int ni = 0; ni < 8; ni++)
#pragma unroll
                for (int q = 0; q < 4; q++) acc[mi][ni][q] = 0.f;

        for (int i = 0; i < NC; i += 2) {
            const int b0 = i & 3, b1 = (i + 1) & 3;
#pragma unroll
            for (int s = 0; s < 8; s++) {       // 8 k16-steps over 2 chunks
                const int cb = s < 4 ? b0 : b1;
                const int nb = (s + 1) < 4 ? b0 : b1;
                const int nk = (s + 1) & 3;
                // half0: mi=0 first so ldB1 sits behind tensor work
#pragma unroll
                for (int ni = 0; ni < 4; ni++)
                    mma_bf16(acc[0][ni], afr[s & 1][0], bfr[ni]);
                ldB1(cb, s & 3);                 // B1(s): 12 MMAs before use
#pragma unroll
                for (int mi = 1; mi < 4; mi++)
#pragma unroll
                    for (int ni = 0; ni < 4; ni++)
                        mma_bf16(acc[mi][ni], afr[s & 1][mi], bfr[ni]);
                if (s == 2 || s == 4) issue_load();   // mid-window: LSU quiet zone
                if (s < 7) {
                    ldA(nb, nk, (s + 1) & 1);    // frags(s+1): 16 MMAs early
                    ldB0(nb, nk);
                } else {
                    // window boundary crossed WITH 16 MMAs still in registers:
                    // wait + barrier + prime next window, then issue half1.
                    CP_WAIT(0);                  // chunks i+2, i+3 resident
                    __syncthreads();             // visibility + buffer release
                    ldA((i + 2) & 3, 0, 0);      // prime next window step 0
                    ldB0((i + 2) & 3, 0);        // (safe across tile boundary)
                }
#pragma unroll
                for (int mi = 0; mi < 4; mi++)   // half1: ni 4..7 (regs only)
#pragma unroll
                    for (int ni = 4; ni < 8; ni++)
                        mma_bf16(acc[mi][ni], afr[s & 1][mi], bfr[ni]);
            }
        }

        // ---- epilogue (next window already primed; loads in flight) ----
        int m0, n0; tile_coords(t, tiles_m, tiles_n, m0, n0);
        const int gr = lane >> 2;
        const int gc = (lane & 3) * 2;
#pragma unroll
        for (int ni = 0; ni < 8; ni++) {
            const int col = n0 + wn * 64 + ni * 8 + gc;
            const float2 bv = *(const float2*)(bias + col);
#pragma unroll
            for (int mi = 0; mi < 4; mi++) {
                const int row = m0 + wm * 64 + mi * 16 + gr;
                stg_cs_f2(out + (size_t)row * N + col,
                          acc[mi][ni][0] + bv.x, acc[mi][ni][1] + bv.y);
                stg_cs_f2(out + (size_t)(row + 8) * N + col,
                          acc[mi][ni][2] + bv.x, acc[mi][ni][3] + bv.y);
            }
        }
    }
}

// ------------------------------ launcher -------------------------------------
extern "C" void kernel_launch(void* const* d_in, const int* in_sizes, int n_in,
                              void* d_out, int out_size) {
    const float* x    = (const float*)d_in[0];   // [B,T,C] f32
    const float* W    = (const float*)d_in[1];   // [O,C]   f32
    const float* bias = (const float*)d_in[2];   // [O]     f32
    float* out = (float*)d_out;                  // [B,T,O] f32

    const int O = in_sizes[2];
    const int C = in_sizes[1] / O;
    const int M = in_sizes[0] / C;

    void *pxb = nullptr, *pwb = nullptr;
    cudaGetSymbolAddress(&pxb, g_Xb);
    cudaGetSymbolAddress(&pwb, g_Wb);

    const int n8x = in_sizes[0] / 8;
    const int n8w = in_sizes[1] / 8;
    const int n8  = n8x + n8w;
    quant_fused_kernel<<<(n8 + 255) / 256, 256>>>(
        x, W, (uint4*)pxb, (uint4*)pwb, n8x, n8w);

    cudaFuncSetAttribute(fp8_gemm_kernel,
                         cudaFuncAttributeMaxDynamicSharedMemorySize, SMEM_TOTAL);

    int nsm = 148;
    cudaDeviceGetAttribute(&nsm, cudaDevAttrMultiProcessorCount, 0);
    const int ntiles = (M / BM) * (O / BN);
    const int blocks = nsm < ntiles ? nsm : ntiles;
    fp8_gemm_kernel<<<blocks, 256, SMEM_TOTAL>>>(bias, out, M, O, C);
}

// round 16
// speedup vs baseline: 1.0936x; 1.0936x over previous
#include <cuda_runtime.h>
#include <cuda_bf16.h>
#include <cuda_fp8.h>
#include <cstdint>

// Problem shape (fixed by the dataset): M=8192 (B*T), K=4096 (C), N=16384 (O)
#define MAX_M 8192
#define MAX_K 4096
#define MAX_N 16384

// bf16 scratch holding fp8-quantized values (e4m3 -> bf16 is exact)
__device__ __align__(128) __nv_bfloat16 g_Xb[(size_t)MAX_M * MAX_K];  //  64 MB
__device__ __align__(128) __nv_bfloat16 g_Wb[(size_t)MAX_N * MAX_K];  // 128 MB

// ----------------------------- helpers -------------------------------------
__device__ __forceinline__ uint32_t smem_u32(const void* p) {
    uint32_t a;
    asm("{ .reg .u64 t; cvta.to.shared.u64 t, %1; cvt.u32.u64 %0, t; }"
        : "=r"(a) : "l"(p));
    return a;
}

#define CP_ASYNC16(saddr, gptr) \
    asm volatile("cp.async.cg.shared.global [%0], [%1], 16;" :: "r"(saddr), "l"(gptr))
#define CP_COMMIT() asm volatile("cp.async.commit_group;" ::: "memory")
#define CP_WAIT(n)  asm volatile("cp.async.wait_group %0;" :: "n"(n) : "memory")

__device__ __forceinline__ void ldsm_x4(uint32_t* r, uint32_t addr) {
    asm volatile("ldmatrix.sync.aligned.m8n8.x4.shared.b16 {%0,%1,%2,%3}, [%4];"
                 : "=r"(r[0]), "=r"(r[1]), "=r"(r[2]), "=r"(r[3]) : "r"(addr));
}

// bf16 x bf16 -> f32 MMA (sm_80+)
__device__ __forceinline__ void mma_bf16(float* c, const uint32_t* a, const uint32_t* b) {
    asm volatile(
        "mma.sync.aligned.m16n8k16.row.col.f32.bf16.bf16.f32 "
        "{%0,%1,%2,%3}, {%4,%5,%6,%7}, {%8,%9}, {%0,%1,%2,%3};"
        : "+f"(c[0]), "+f"(c[1]), "+f"(c[2]), "+f"(c[3])
        : "r"(a[0]), "r"(a[1]), "r"(a[2]), "r"(a[3]), "r"(b[0]), "r"(b[1]));
}

// streaming (evict-first) float2 store: out is write-once, keep it out of L2
__device__ __forceinline__ void stg_cs_f2(float* p, float a, float b) {
    asm volatile("st.global.cs.v2.f32 [%0], {%1, %2};"
                 :: "l"(p), "f"(a), "f"(b) : "memory");
}

// ------------------------------ constants -----------------------------------
// CTA tile 256x128, 8 warps (4M x 2N), warp tile 64x64. Persistent CTAs.
#define BM 256
#define BN 128
#define BKB 128                                 // chunk K-bytes per row
#define STAGES 4
#define STAGE_A (BM * BKB)                      // 32768
#define STAGE_B (BN * BKB)                      // 16384
#define STAGE_BYTES (STAGE_A + STAGE_B)         // 49152
#define SMEM_TOTAL (STAGES * STAGE_BYTES)       // 196608
#define GRP 8

// ------------------------------ quantize ------------------------------------
// x -> clamp/round to e4m3 (satfinite) -> bf16 (exact). Matches reference
// fp8 quantize->dequantize semantics bit-for-bit.
__device__ __forceinline__ uint32_t q2bf(float a, float b) {
    __nv_fp8x2_storage_t p8 =
        __nv_cvt_float2_to_fp8x2(make_float2(a, b), __NV_SATFINITE, __NV_E4M3);
    __half2_raw hr = __nv_cvt_fp8x2_to_halfraw2(p8, __NV_E4M3);   // exact
    __half2 h = *reinterpret_cast<__half2*>(&hr);
    float2 f = __half22float2(h);                                  // exact
    __nv_bfloat162 bb = __float22bfloat162_rn(f);                  // exact (e4m3)
    return *reinterpret_cast<uint32_t*>(&bb);
}

// each thread: 2 adjacent float4 reads (32B) -> 1 uint4 write (16B)
__global__ void quant_fused_kernel(const float* __restrict__ x,
                                   const float* __restrict__ w,
                                   uint4* __restrict__ xb,
                                   uint4* __restrict__ wb,
                                   int n8x, int n8w) {
    int i = blockIdx.x * blockDim.x + threadIdx.x;
    if (i < n8x) {
        float4 v0 = ((const float4*)x)[2 * i];
        float4 v1 = ((const float4*)x)[2 * i + 1];
        xb[i] = make_uint4(q2bf(v0.x, v0.y), q2bf(v0.z, v0.w),
                           q2bf(v1.x, v1.y), q2bf(v1.z, v1.w));
    } else {
        int j = i - n8x;
        if (j < n8w) {
            float4 v0 = ((const float4*)w)[2 * j];
            float4 v1 = ((const float4*)w)[2 * j + 1];
            wb[j] = make_uint4(q2bf(v0.x, v0.y), q2bf(v0.z, v0.w),
                               q2bf(v1.x, v1.y), q2bf(v1.z, v1.w));
        }
    }
}

// grouped rasterization: tile id -> (m0, n0)
__device__ __forceinline__ void tile_coords(int t, int tiles_m, int tiles_n,
                                            int& m0, int& n0) {
    int tpg = GRP * tiles_n;
    int g = t / tpg, r = t % tpg;
    int mf = g * GRP;
    int gs = tiles_m - mf; if (gs > GRP) gs = GRP;
    m0 = (mf + (r % gs)) * BM;
    n0 = (r / gs) * BN;
}

// ------------------------------- GEMM ----------------------------------------
__global__ void __launch_bounds__(256, 1)
fp8_gemm_kernel(const float* __restrict__ bias, float* __restrict__ out,
                int M, int N, int K) {
    extern __shared__ char smem[];
    const uint32_t sbase = smem_u32(smem);
    const int tid  = threadIdx.x;
    const int wid  = tid >> 5;
    const int lane = tid & 31;
    const int wm = wid & 3;    // 4 M-warps x 64 rows
    const int wn = wid >> 2;   // 2 N-warps x 64 cols

    const int tiles_m = M / BM;   // 32
    const int tiles_n = N / BN;   // 128
    const int ntiles  = tiles_m * tiles_n;
    const int G = gridDim.x;
    const size_t rowbytes = (size_t)K * 2;
    const int NC = (K * 2) / BKB;   // 64 chunks of 64 bf16

    // ---- load-side cursor (rolls across tile boundaries) ----
    int t_load = blockIdx.x;
    int ck_load = 0;
    const uint8_t *lAg, *lBg;
    {
        int m0l, n0l; tile_coords(t_load, tiles_m, tiles_n, m0l, n0l);
        lAg = (const uint8_t*)g_Xb + (size_t)m0l * rowbytes;
        lBg = (const uint8_t*)g_Wb + (size_t)n0l * rowbytes;
    }

    // one K-chunk: 3072 x 16B units (A 2048 + B 1024); 12 per thread.
    // smem rows 128B; swizzle cu = c ^ (row & 7) -> conflict-free.
    auto issue_load = [&]() {
        if (t_load < ntiles) {
            const uint32_t st = sbase + (ck_load & 3) * STAGE_BYTES;
            const int ck = ck_load;
#pragma unroll
            for (int j = 0; j < 12; j++) {
                int u = tid + 256 * j;
                if (u < 2048) {
                    int row = u >> 3, c = u & 7;
                    CP_ASYNC16(st + row * 128 + ((c ^ (row & 7)) << 4),
                               lAg + (size_t)row * rowbytes + ck * BKB + c * 16);
                } else {
                    int v = u - 2048;
                    int row = v >> 3, c = v & 7;
                    CP_ASYNC16(st + STAGE_A + row * 128 + ((c ^ (row & 7)) << 4),
                               lBg + (size_t)row * rowbytes + ck * BKB + c * 16);
                }
            }
            if (++ck_load == NC) {
                ck_load = 0;
                t_load += G;
                if (t_load < ntiles) {
                    int m0l, n0l; tile_coords(t_load, tiles_m, tiles_n, m0l, n0l);
                    lAg = (const uint8_t*)g_Xb + (size_t)m0l * rowbytes;
                    lBg = (const uint8_t*)g_Wb + (size_t)n0l * rowbytes;
                }
            }
        }
        CP_COMMIT();
    };

    // lane-derived ldmatrix address components (mapping verified rel_err=0)
    const int lr   = lane & 7;
    const int lsel = lane >> 3;                 // 0..3
    const int a_row_off = lr + (lsel & 1) * 8;  // A: bit0 -> +8 rows
    const int a_ku      = lsel >> 1;            //    bit1 -> k-unit
    const int b_ni_off  = lsel >> 1;            // B: bit1 -> n8 within pair
    const int b_ku      = lsel & 1;             //    bit0 -> k-unit
    const uint32_t a_base = (uint32_t)(wm * 64 + a_row_off) * 128;
    const uint32_t b_base = STAGE_A + (uint32_t)(wn * 64 + b_ni_off * 8 + lr) * 128;

    float acc[4][8][4];
    uint32_t afr[2][4][4];
    uint32_t bfr[8][2];

    auto ldA = [&](int buf, int ks, int pb) {
        const uint32_t s = sbase + buf * STAGE_BYTES + a_base
                         + ((((ks << 1) | a_ku) ^ lr) << 4);
#pragma unroll
        for (int mi = 0; mi < 4; mi++)
            ldsm_x4(afr[pb][mi], s + mi * 2048);
    };
    auto ldB0 = [&](int buf, int ks) {
        const uint32_t s = sbase + buf * STAGE_BYTES + b_base
                         + ((((ks << 1) | b_ku) ^ lr) << 4);
        uint32_t t[4];
        ldsm_x4(t, s);
        bfr[0][0] = t[0]; bfr[0][1] = t[1]; bfr[1][0] = t[2]; bfr[1][1] = t[3];
        ldsm_x4(t, s + 2048);
        bfr[2][0] = t[0]; bfr[2][1] = t[1]; bfr[3][0] = t[2]; bfr[3][1] = t[3];
    };
    auto ldB1 = [&](int buf, int ks) {
        const uint32_t s = sbase + buf * STAGE_BYTES + b_base
                         + ((((ks << 1) | b_ku) ^ lr) << 4);
        uint32_t t[4];
        ldsm_x4(t, s + 4096);
        bfr[4][0] = t[0]; bfr[4][1] = t[1]; bfr[5][0] = t[2]; bfr[5][1] = t[3];
        ldsm_x4(t, s + 6144);
        bfr[6][0] = t[0]; bfr[6][1] = t[1]; bfr[7][0] = t[2]; bfr[7][1] = t[3];
    };

    // ---- prologue: 2 chunks in flight, prime first window ----
    issue_load();
    issue_load();
    CP_WAIT(0);
    __syncthreads();
    ldA(0, 0, 0); ldB0(0, 0);

    // ---- persistent tile loop ----
    for (int t = blockIdx.x; t < ntiles; t += G) {
#pragma unroll
        for (int mi = 0; mi < 4; mi++)
#pragma unroll
            for (int ni = 0; ni < 8; ni++)
#pragma unroll
                for (int q = 0; q < 4; q++) acc[mi][ni][q] = 0.f;

        for (int i = 0; i < NC; i += 2) {
            const int b0 = i & 3, b1 = (i + 1) & 3;
#pragma unroll
            for (int s = 0; s < 8; s++) {       // 8 k16-steps over 2 chunks
                const int cb = s < 4 ? b0 : b1;
                const int nb = (s + 1) < 4 ? b0 : b1;
                const int nk = (s + 1) & 3;
                // half0: mi=0 first so ldB1 sits behind tensor work
#pragma unroll
                for (int ni = 0; ni < 4; ni++)
                    mma_bf16(acc[0][ni], afr[s & 1][0], bfr[ni]);
                ldB1(cb, s & 3);                 // B1(s): 12 MMAs before use
#pragma unroll
                for (int mi = 1; mi < 4; mi++)
#pragma unroll
                    for (int ni = 0; ni < 4; ni++)
                        mma_bf16(acc[mi][ni], afr[s & 1][mi], bfr[ni]);
                if (s == 0 || s == 2) issue_load();   // early chunk lookahead
                if (s < 7) {
                    ldA(nb, nk, (s + 1) & 1);    // frags(s+1): 16 MMAs early
                    ldB0(nb, nk);
                } else {
                    // window boundary crossed WITH 16 MMAs still in registers:
                    // wait + barrier + prime next window, then issue half1.
                    CP_WAIT(0);                  // chunks i+2, i+3 resident
                    __syncthreads();             // visibility + buffer release
                    ldA((i + 2) & 3, 0, 0);      // prime next window step 0
                    ldB0((i + 2) & 3, 0);        // (safe across tile boundary)
                }
#pragma unroll
                for (int mi = 0; mi < 4; mi++)   // half1: ni 4..7 (regs only)
#pragma unroll
                    for (int ni = 4; ni < 8; ni++)
                        mma_bf16(acc[mi][ni], afr[s & 1][mi], bfr[ni]);
            }
        }

        // ---- epilogue (next window already primed; loads in flight) ----
        int m0, n0; tile_coords(t, tiles_m, tiles_n, m0, n0);
        const int gr = lane >> 2;
        const int gc = (lane & 3) * 2;
#pragma unroll
        for (int ni = 0; ni < 8; ni++) {
            const int col = n0 + wn * 64 + ni * 8 + gc;
            const float2 bv = *(const float2*)(bias + col);
#pragma unroll
            for (int mi = 0; mi < 4; mi++) {
                const int row = m0 + wm * 64 + mi * 16 + gr;
                stg_cs_f2(out + (size_t)row * N + col,
                          acc[mi][ni][0] + bv.x, acc[mi][ni][1] + bv.y);
                stg_cs_f2(out + (size_t)(row + 8) * N + col,
                          acc[mi][ni][2] + bv.x, acc[mi][ni][3] + bv.y);
            }
        }
    }
}

// ------------------------------ launcher -------------------------------------
extern "C" void kernel_launch(void* const* d_in, const int* in_sizes, int n_in,
                              void* d_out, int out_size) {
    const float* x    = (const float*)d_in[0];   // [B,T,C] f32
    const float* W    = (const float*)d_in[1];   // [O,C]   f32
    const float* bias = (const float*)d_in[2];   // [O]     f32
    float* out = (float*)d_out;                  // [B,T,O] f32

    const int O = in_sizes[2];
    const int C = in_sizes[1] / O;
    const int M = in_sizes[0] / C;

    void *pxb = nullptr, *pwb = nullptr;
    cudaGetSymbolAddress(&pxb, g_Xb);
    cudaGetSymbolAddress(&pwb, g_Wb);

    const int n8x = in_sizes[0] / 8;
    const int n8w = in_sizes[1] / 8;
    const int n8  = n8x + n8w;
    quant_fused_kernel<<<(n8 + 255) / 256, 256>>>(
        x, W, (uint4*)pxb, (uint4*)pwb, n8x, n8w);

    cudaFuncSetAttribute(fp8_gemm_kernel,
                         cudaFuncAttributeMaxDynamicSharedMemorySize, SMEM_TOTAL);

    int nsm = 148;
    cudaDeviceGetAttribute(&nsm, cudaDevAttrMultiProcessorCount, 0);
    const int ntiles = (M / BM) * (O / BN);
    const int blocks = nsm < ntiles ? nsm : ntiles;
    fp8_gemm_kernel<<<blocks, 256, SMEM_TOTAL>>>(bias, out, M, O, C);
}